// round 15
// baseline (speedup 1.0000x reference)
#include <cuda_runtime.h>
#include <cuda_bf16.h>
#include <cuda_fp16.h>
#include <cstdint>

#define B_ 4
#define C_ 64
#define N_ 40960
#define K_ 16
#define D_ 128
#define EPS_ 1e-5f
#define NT_ 64
#define K1TILES_ 2560          // B_ * N_/64
#define K2TILES_ 2560
#define POOL_ (K1TILES_ + K2TILES_)
#define GRID_ 456

// ---------------- global scratch ----------------
__device__ __half g_p[(size_t)B_ * N_ * C_];   // relu(BN1(w1@f)) per point, fp16 128B rows
__device__ int g_pool = 0;
__device__ int g_done = 0;
__device__ int g_k1done[B_] = {0, 0, 0, 0};

// ---------------- helpers ----------------
__device__ __forceinline__ void mma16816(float* d, const uint32_t* a, const uint32_t* b) {
    asm volatile(
        "mma.sync.aligned.m16n8k16.row.col.f32.f16.f16.f32 "
        "{%0,%1,%2,%3}, {%4,%5,%6,%7}, {%8,%9}, {%0,%1,%2,%3};\n"
        : "+f"(d[0]), "+f"(d[1]), "+f"(d[2]), "+f"(d[3])
        : "r"(a[0]), "r"(a[1]), "r"(a[2]), "r"(a[3]), "r"(b[0]), "r"(b[1]));
}

__device__ __forceinline__ void ldsm4(uint32_t* r, uint32_t addr) {
    asm volatile("ldmatrix.sync.aligned.m8n8.x4.shared.b16 {%0,%1,%2,%3}, [%4];"
                 : "=r"(r[0]), "=r"(r[1]), "=r"(r[2]), "=r"(r[3]) : "r"(addr));
}

__device__ __forceinline__ uint32_t smem_u32(const void* p) {
    uint32_t a;
    asm("{ .reg .u64 t; cvta.to.shared.u64 t, %1; cvt.u32.u64 %0, t; }" : "=r"(a) : "l"(p));
    return a;
}

// ---------------- smem layout (single fused kernel) ----------------
#define SW_ 144
#define W1_ 0          // 64 x 144  = 9216
#define W2_ 9216       // 128 x 144 = 18432
#define W3_ 27648      // 128 x 144 = 18432
#define XH_ 46080      // 64 x 144  = 9216  (K2 gather out; K1 epilogue staging)
#define XF_ 55296      // 64 x 144  = 9216  (transposed f tile, both paths)
#define CTRL_ 64512
#define SMEM_ 64544

__global__ __launch_bounds__(256, 3) void fused_kernel(
    const float* __restrict__ f, const int* __restrict__ nidx, float* __restrict__ out,
    const float* __restrict__ w1, const float* __restrict__ g1, const float* __restrict__ b1,
    const float* __restrict__ m1, const float* __restrict__ v1,
    const float* __restrict__ w2, const float* __restrict__ g2, const float* __restrict__ b2,
    const float* __restrict__ m2, const float* __restrict__ v2,
    const float* __restrict__ w3, const float* __restrict__ g3, const float* __restrict__ b3,
    const float* __restrict__ m3, const float* __restrict__ v3) {
    extern __shared__ __align__(16) char smem[];
    const int tid = threadIdx.x;
    const int wid = tid >> 5, lane = tid & 31;
    const int g = lane >> 2, q = lane & 3;
    const uint32_t sb = smem_u32(smem);

    // per-lane ldmatrix offsets (bytes)
    const uint32_t a_lane = (lane & 7) * SW_ + ((lane >> 3) & 1) * (8 * SW_) + (lane >> 4) * 16;
    const uint32_t b_lane = ((lane >> 4) * 8 + (lane & 7)) * SW_ + ((lane >> 3) & 1) * 16;

    // ---- stage fused fp16 weights (once per CTA) ----
    #pragma unroll
    for (int i = tid; i < C_ * C_; i += 256) {
        int o = i >> 6, c = i & 63;
        float sc = g1[o] * rsqrtf(v1[o] + EPS_);
        *(__half*)(smem + W1_ + o * SW_ + c * 2) = __float2half(w1[i] * sc);
    }
    #pragma unroll
    for (int i = tid; i < D_ * C_; i += 256) {
        int o = i >> 6, c = i & 63;
        float sc2 = g2[o] * rsqrtf(v2[o] + EPS_);
        *(__half*)(smem + W2_ + o * SW_ + c * 2) = __float2half(w2[i] * sc2);
        float sc3 = g3[o] * rsqrtf(v3[o] + EPS_);
        *(__half*)(smem + W3_ + o * SW_ + c * 2) = __float2half(w3[i] * sc3);
    }

    // ---- persistent BN shifts ----
    // K1 path indexing: mq1 = wid>>2 (32-row half), ns1 = wid&3 (16-pt group)
    const int mq1 = wid >> 2, ns1 = wid & 3;
    float sh1r[2][2];
    #pragma unroll
    for (int mt = 0; mt < 2; ++mt) {
        int o = mq1 * 32 + mt * 16 + g;
        sh1r[mt][0] = b1[o] - m1[o] * (g1[o] * rsqrtf(v1[o] + EPS_));
        sh1r[mt][1] = b1[o + 8] - m1[o + 8] * (g1[o + 8] * rsqrtf(v1[o + 8] + EPS_));
    }
    // K2 path indexing: mq2 = wid>>1 (32-row quarter of 128), ns2 = wid&1 (32-pt half)
    const int mq2 = wid >> 1, ns2 = wid & 1;
    float sh2r[2][2], sh3r[2][2];
    #pragma unroll
    for (int mt = 0; mt < 2; ++mt) {
        int o = mq2 * 32 + mt * 16 + g;
        sh2r[mt][0] = b2[o] - m2[o] * (g2[o] * rsqrtf(v2[o] + EPS_));
        sh2r[mt][1] = b2[o + 8] - m2[o + 8] * (g2[o + 8] * rsqrtf(v2[o + 8] + EPS_));
        sh3r[mt][0] = b3[o] - m3[o] * (g3[o] * rsqrtf(v3[o] + EPS_));
        sh3r[mt][1] = b3[o + 8] - m3[o + 8] * (g3[o + 8] * rsqrtf(v3[o + 8] + EPS_));
    }
    int* ctrl = (int*)(smem + CTRL_);

    for (;;) {
        __syncthreads();   // protect smem data regions from previous tile
        if (tid == 0) {
            int t = atomicAdd(&g_pool, 1);
            ctrl[0] = t;
            if (t >= K1TILES_ && t < POOL_) {
                int b = (t - K1TILES_) / (N_ / NT_);
                while (*(volatile int*)&g_k1done[b] < (N_ / NT_)) __nanosleep(128);
            }
        }
        __syncthreads();
        const int t = ctrl[0];
        if (t >= POOL_) break;

        if (t < K1TILES_) {
            // ================= K1 tile: p = relu(BN1(w1 @ f)), 64 points =================
            const int b = t / (N_ / NT_);
            const int n0 = (t % (N_ / NT_)) * NT_;

            // transpose f tile -> XF fp16 [pt][ch]
            const float* fb = f + (size_t)b * C_ * N_ + n0;
            #pragma unroll
            for (int it = 0; it < 8; ++it) {
                int idx = it * 256 + tid;
                int j = idx & 63, c = (idx >> 6) * 2;
                float x0 = fb[(size_t)c * N_ + j];
                float x1 = fb[(size_t)(c + 1) * N_ + j];
                __half2 h2 = __floats2half2_rn(x0, x1);
                *(uint32_t*)(smem + XF_ + j * SW_ + c * 2) = *(uint32_t*)&h2;
            }
            __syncthreads();

            // MMA: warp = rows [mq1*32,+32) x pts [ns1*16,+16)
            float acc[2][2][4];
            #pragma unroll
            for (int mt = 0; mt < 2; ++mt)
                #pragma unroll
                for (int nt = 0; nt < 2; ++nt)
                    #pragma unroll
                    for (int e = 0; e < 4; ++e) acc[mt][nt][e] = 0.f;
            #pragma unroll
            for (int k = 0; k < 4; ++k) {
                const uint32_t kb = 32 * k;
                uint32_t Ar[2][4], Br[4];
                ldsm4(Ar[0], sb + W1_ + (uint32_t)(mq1 * 32) * SW_ + kb + a_lane);
                ldsm4(Ar[1], sb + W1_ + (uint32_t)(mq1 * 32 + 16) * SW_ + kb + a_lane);
                ldsm4(Br, sb + XF_ + (uint32_t)(ns1 * 16) * SW_ + kb + b_lane);
                #pragma unroll
                for (int mt = 0; mt < 2; ++mt)
                    #pragma unroll
                    for (int nt = 0; nt < 2; ++nt)
                        mma16816(acc[mt][nt], Ar[mt], &Br[nt * 2]);
            }

            // epilogue: relu(acc+sh1) -> fp16 -> XH region [pt][o]
            #pragma unroll
            for (int mt = 0; mt < 2; ++mt) {
                int o = mq1 * 32 + mt * 16 + g;
                #pragma unroll
                for (int nt = 0; nt < 2; ++nt) {
                    int pt = ns1 * 16 + nt * 8 + q * 2;
                    *(__half*)(smem + XH_ + pt * SW_ + o * 2) =
                        __float2half(fmaxf(acc[mt][nt][0] + sh1r[mt][0], 0.f));
                    *(__half*)(smem + XH_ + (pt + 1) * SW_ + o * 2) =
                        __float2half(fmaxf(acc[mt][nt][1] + sh1r[mt][0], 0.f));
                    *(__half*)(smem + XH_ + pt * SW_ + (o + 8) * 2) =
                        __float2half(fmaxf(acc[mt][nt][2] + sh1r[mt][1], 0.f));
                    *(__half*)(smem + XH_ + (pt + 1) * SW_ + (o + 8) * 2) =
                        __float2half(fmaxf(acc[mt][nt][3] + sh1r[mt][1], 0.f));
                }
            }
            __syncthreads();

            // coalesced store: 64 rows x 128B -> g_p
            __half* pb = g_p + ((size_t)b * N_ + n0) * 64;
            #pragma unroll
            for (int it = 0; it < 2; ++it) {
                int i = it * 256 + tid;
                int row = i >> 3, e = i & 7;
                *(uint4*)(pb + (size_t)row * 64 + e * 8) =
                    *(const uint4*)(smem + XH_ + row * SW_ + e * 16);
            }
            __threadfence();
            __syncthreads();
            if (tid == 0) atomicAdd(&g_k1done[b], 1);
        } else {
            // ================= K2 tile: out = relu(BN2(w2@hsum)) + relu(BN3(w3@f)) =================
            const int t2 = t - K1TILES_;
            const int b = t2 / (N_ / NT_);
            const int n0 = (t2 % (N_ / NT_)) * NT_;

            // transpose f tile -> XF fp16
            const float* fb = f + (size_t)b * C_ * N_ + n0;
            #pragma unroll
            for (int it = 0; it < 8; ++it) {
                int idx = it * 256 + tid;
                int j = idx & 63, c = (idx >> 6) * 2;
                float x0 = fb[(size_t)c * N_ + j];
                float x1 = fb[(size_t)(c + 1) * N_ + j];
                __half2 h2 = __floats2half2_rn(x0, x1);
                *(uint32_t*)(smem + XF_ + j * SW_ + c * 2) = *(uint32_t*)&h2;
            }

            // gather-sum p: 8 lanes per 128B row, fp32 accumulate -> XH fp16
            {
                const int e = tid & 7;
                const __half* pbase = g_p + (size_t)b * N_ * 64 + e * 8;
                const int4* ibase = (const int4*)(nidx + ((size_t)b * N_ + n0) * 16);
                #pragma unroll
                for (int p4 = 0; p4 < 2; ++p4) {
                    const int j = (tid >> 3) + p4 * 32;
                    int4 id4[4];
                    #pragma unroll
                    for (int u = 0; u < 4; ++u) id4[u] = ibase[j * 4 + u];
                    int ids[16] = {id4[0].x, id4[0].y, id4[0].z, id4[0].w,
                                   id4[1].x, id4[1].y, id4[1].z, id4[1].w,
                                   id4[2].x, id4[2].y, id4[2].z, id4[2].w,
                                   id4[3].x, id4[3].y, id4[3].z, id4[3].w};
                    float2 acc[4];
                    #pragma unroll
                    for (int u = 0; u < 4; ++u) acc[u] = make_float2(0.f, 0.f);
                    #pragma unroll
                    for (int k = 0; k < 16; ++k) {
                        uint4 v = *(const uint4*)(pbase + (size_t)ids[k] * 64);
                        const __half2* hp = (const __half2*)&v;
                        #pragma unroll
                        for (int u = 0; u < 4; ++u) {
                            float2 fv = __half22float2(hp[u]);
                            acc[u].x += fv.x;
                            acc[u].y += fv.y;
                        }
                    }
                    __half2 hh[4];
                    #pragma unroll
                    for (int u = 0; u < 4; ++u)
                        hh[u] = __floats2half2_rn(acc[u].x, acc[u].y);
                    *(uint4*)(smem + XH_ + j * SW_ + e * 16) = *(uint4*)hh;
                }
            }
            __syncthreads();

            // sequential GEMMs (shared acc block)
            const int obase = mq2 * 32;
            float* outb = out + (size_t)b * D_ * N_ + n0;
            float acc[2][4][4];
            uint32_t sreg[2][4][2];

            // GEMM2: W3 x F -> packed partial
            #pragma unroll
            for (int mt = 0; mt < 2; ++mt)
                #pragma unroll
                for (int nt = 0; nt < 4; ++nt)
                    #pragma unroll
                    for (int e = 0; e < 4; ++e) acc[mt][nt][e] = 0.f;
            #pragma unroll
            for (int k = 0; k < 4; ++k) {
                const uint32_t kb = 32 * k;
                uint32_t Ar[2][4], Br[2][4];
                ldsm4(Ar[0], sb + W3_ + (uint32_t)obase * SW_ + kb + a_lane);
                ldsm4(Ar[1], sb + W3_ + (uint32_t)(obase + 16) * SW_ + kb + a_lane);
                ldsm4(Br[0], sb + XF_ + (uint32_t)(ns2 * 32) * SW_ + kb + b_lane);
                ldsm4(Br[1], sb + XF_ + (uint32_t)(ns2 * 32 + 16) * SW_ + kb + b_lane);
                #pragma unroll
                for (int mt = 0; mt < 2; ++mt)
                    #pragma unroll
                    for (int nt = 0; nt < 4; ++nt)
                        mma16816(acc[mt][nt], Ar[mt], &Br[nt >> 1][(nt & 1) * 2]);
            }
            #pragma unroll
            for (int mt = 0; mt < 2; ++mt)
                #pragma unroll
                for (int nt = 0; nt < 4; ++nt) {
                    __half2 p0 = __floats2half2_rn(fmaxf(acc[mt][nt][0] + sh3r[mt][0], 0.f),
                                                   fmaxf(acc[mt][nt][1] + sh3r[mt][0], 0.f));
                    __half2 p1 = __floats2half2_rn(fmaxf(acc[mt][nt][2] + sh3r[mt][1], 0.f),
                                                   fmaxf(acc[mt][nt][3] + sh3r[mt][1], 0.f));
                    sreg[mt][nt][0] = *(uint32_t*)&p0;
                    sreg[mt][nt][1] = *(uint32_t*)&p1;
                }

            // GEMM1: W2 x Hsum (reuse acc)
            #pragma unroll
            for (int mt = 0; mt < 2; ++mt)
                #pragma unroll
                for (int nt = 0; nt < 4; ++nt)
                    #pragma unroll
                    for (int e = 0; e < 4; ++e) acc[mt][nt][e] = 0.f;
            #pragma unroll
            for (int k = 0; k < 4; ++k) {
                const uint32_t kb = 32 * k;
                uint32_t Ar[2][4], Br[2][4];
                ldsm4(Ar[0], sb + W2_ + (uint32_t)obase * SW_ + kb + a_lane);
                ldsm4(Ar[1], sb + W2_ + (uint32_t)(obase + 16) * SW_ + kb + a_lane);
                ldsm4(Br[0], sb + XH_ + (uint32_t)(ns2 * 32) * SW_ + kb + b_lane);
                ldsm4(Br[1], sb + XH_ + (uint32_t)(ns2 * 32 + 16) * SW_ + kb + b_lane);
                #pragma unroll
                for (int mt = 0; mt < 2; ++mt)
                    #pragma unroll
                    for (int nt = 0; nt < 4; ++nt)
                        mma16816(acc[mt][nt], Ar[mt], &Br[nt >> 1][(nt & 1) * 2]);
            }

            // epilogue: res = relu(h+sh2) + partial_s
            #pragma unroll
            for (int mt = 0; mt < 2; ++mt) {
                int o = obase + mt * 16 + g;
                #pragma unroll
                for (int nt = 0; nt < 4; ++nt) {
                    int col = ns2 * 32 + nt * 8 + q * 2;
                    float2 s0 = __half22float2(*(__half2*)&sreg[mt][nt][0]);
                    float2 s1 = __half22float2(*(__half2*)&sreg[mt][nt][1]);
                    float2 v0, v1;
                    v0.x = fmaxf(acc[mt][nt][0] + sh2r[mt][0], 0.f) + s0.x;
                    v0.y = fmaxf(acc[mt][nt][1] + sh2r[mt][0], 0.f) + s0.y;
                    v1.x = fmaxf(acc[mt][nt][2] + sh2r[mt][1], 0.f) + s1.x;
                    v1.y = fmaxf(acc[mt][nt][3] + sh2r[mt][1], 0.f) + s1.y;
                    *(float2*)(outb + (size_t)o * N_ + col) = v0;
                    *(float2*)(outb + (size_t)(o + 8) * N_ + col) = v1;
                }
            }
        }
    }

    // ---- reset counters for next graph replay (last CTA out) ----
    __syncthreads();
    if (tid == 0) {
        if (atomicAdd(&g_done, 1) == GRID_ - 1) {
            g_pool = 0;
            g_done = 0;
            #pragma unroll
            for (int i = 0; i < B_; ++i) g_k1done[i] = 0;
            __threadfence();
        }
    }
}

extern "C" void kernel_launch(void* const* d_in, const int* in_sizes, int n_in,
                              void* d_out, int out_size) {
    const float* feature = (const float*)d_in[0];
    const int* nidx = (const int*)d_in[1];
    const float* w1 = (const float*)d_in[2];
    const float* g1 = (const float*)d_in[3];
    const float* b1 = (const float*)d_in[4];
    const float* m1 = (const float*)d_in[5];
    const float* v1 = (const float*)d_in[6];
    const float* w2 = (const float*)d_in[7];
    const float* g2 = (const float*)d_in[8];
    const float* b2 = (const float*)d_in[9];
    const float* m2 = (const float*)d_in[10];
    const float* v2 = (const float*)d_in[11];
    const float* w3 = (const float*)d_in[12];
    const float* g3 = (const float*)d_in[13];
    const float* b3 = (const float*)d_in[14];
    const float* m3 = (const float*)d_in[15];
    const float* v3 = (const float*)d_in[16];
    float* out = (float*)d_out;

    cudaFuncSetAttribute(fused_kernel, cudaFuncAttributeMaxDynamicSharedMemorySize, SMEM_);
    fused_kernel<<<GRID_, 256, SMEM_>>>(feature, nidx, out,
                                        w1, g1, b1, m1, v1,
                                        w2, g2, b2, m2, v2,
                                        w3, g3, b3, m3, v3);
}

// round 16
// speedup vs baseline: 1.0475x; 1.0475x over previous
#include <cuda_runtime.h>
#include <cuda_bf16.h>
#include <cuda_fp16.h>
#include <cstdint>

#define B_ 4
#define C_ 64
#define N_ 40960
#define K_ 16
#define D_ 128
#define EPS_ 1e-5f
#define NT_ 64
#define TILES_ 2560   // B_ * N_/NT_

// ---------------- global scratch ----------------
__device__ __half g_p[(size_t)B_ * N_ * C_];   // relu(BN1(w1@f)) per point, fp16 128B rows
__device__ int g_ticket = 0;

// ---------------- helpers ----------------
__device__ __forceinline__ void mma16816(float* d, const uint32_t* a, const uint32_t* b) {
    asm volatile(
        "mma.sync.aligned.m16n8k16.row.col.f32.f16.f16.f32 "
        "{%0,%1,%2,%3}, {%4,%5,%6,%7}, {%8,%9}, {%0,%1,%2,%3};\n"
        : "+f"(d[0]), "+f"(d[1]), "+f"(d[2]), "+f"(d[3])
        : "r"(a[0]), "r"(a[1]), "r"(a[2]), "r"(a[3]), "r"(b[0]), "r"(b[1]));
}

__device__ __forceinline__ void ldsm4(uint32_t* r, uint32_t addr) {
    asm volatile("ldmatrix.sync.aligned.m8n8.x4.shared.b16 {%0,%1,%2,%3}, [%4];"
                 : "=r"(r[0]), "=r"(r[1]), "=r"(r[2]), "=r"(r[3]) : "r"(addr));
}

__device__ __forceinline__ uint32_t smem_u32(const void* p) {
    uint32_t a;
    asm("{ .reg .u64 t; cvta.to.shared.u64 t, %1; cvt.u32.u64 %0, t; }" : "=r"(a) : "l"(p));
    return a;
}

__device__ __forceinline__ uint4 hadd2_u4(uint4 a, uint4 b) {
    uint4 r;
    const __half2* ra = (const __half2*)&a;
    const __half2* rb = (const __half2*)&b;
    __half2* rr = (__half2*)&r;
    rr[0] = __hadd2(ra[0], rb[0]);
    rr[1] = __hadd2(ra[1], rb[1]);
    rr[2] = __hadd2(ra[2], rb[2]);
    rr[3] = __hadd2(ra[3], rb[3]);
    return r;
}

// ---------------- K1: p = relu(BN1(w1 @ f)) via fp16 HMMA; inline weight fusion ----------------
// Tile = 128 points. XF/XP [pt][ch] fp16, 144B pitch; W1 [o][c] fp16, 144B pitch.
#define SW_ 144
#define K1W1_ 0
#define K1XF_ 9216
#define K1XP_ 27648
#define SMEM1_ 46080

__global__ __launch_bounds__(256, 2) void k1_kernel(const float* __restrict__ f,
                                                    const float* __restrict__ w1,
                                                    const float* __restrict__ g1,
                                                    const float* __restrict__ b1,
                                                    const float* __restrict__ m1,
                                                    const float* __restrict__ v1) {
    extern __shared__ __align__(16) char smem[];
    const int tid = threadIdx.x;
    const int wid = tid >> 5, lane = tid & 31;
    const int g = lane >> 2, q = lane & 3;
    const int mq = wid >> 2, ns = wid & 3;
    const int b = blockIdx.y;
    const int n0 = blockIdx.x * 128;

    if (blockIdx.x == 0 && blockIdx.y == 0 && tid == 0) g_ticket = 0;

    // fuse + convert w1 -> fp16 padded smem (per block)
    #pragma unroll
    for (int i = tid; i < C_ * C_; i += 256) {
        int o = i >> 6, c = i & 63;
        float sc = g1[o] * rsqrtf(v1[o] + EPS_);
        *(__half*)(smem + K1W1_ + o * SW_ + c * 2) = __float2half(w1[i] * sc);
    }
    float sh1r[2][2];
    #pragma unroll
    for (int mt = 0; mt < 2; ++mt) {
        int o = mq * 32 + mt * 16 + g;
        sh1r[mt][0] = b1[o] - m1[o] * (g1[o] * rsqrtf(v1[o] + EPS_));
        sh1r[mt][1] = b1[o + 8] - m1[o + 8] * (g1[o + 8] * rsqrtf(v1[o + 8] + EPS_));
    }

    // transpose f tile -> XF fp16 [pt][ch]
    const float* fb = f + (size_t)b * C_ * N_ + n0;
    #pragma unroll
    for (int it = 0; it < 16; ++it) {
        int idx = it * 256 + tid;
        int j = idx & 127, c = (idx >> 7) * 2;
        float x0 = fb[(size_t)c * N_ + j];
        float x1 = fb[(size_t)(c + 1) * N_ + j];
        __half2 h2 = __floats2half2_rn(x0, x1);
        *(uint32_t*)(smem + K1XF_ + j * SW_ + c * 2) = *(uint32_t*)&h2;
    }
    __syncthreads();

    // MMA: warp = rows [mq*32,+32) x pts [ns*32,+32)
    float acc[2][4][4];
    #pragma unroll
    for (int mt = 0; mt < 2; ++mt)
        #pragma unroll
        for (int nt = 0; nt < 4; ++nt)
            #pragma unroll
            for (int e = 0; e < 4; ++e) acc[mt][nt][e] = 0.f;

    #pragma unroll
    for (int k = 0; k < 4; ++k) {
        const int koff = 32 * k + 4 * q;
        uint32_t A[2][4], Bv[4][2];
        #pragma unroll
        for (int mt = 0; mt < 2; ++mt) {
            int rb = (mq * 32 + mt * 16 + g) * SW_ + koff;
            A[mt][0] = *(uint32_t*)(smem + K1W1_ + rb);
            A[mt][1] = *(uint32_t*)(smem + K1W1_ + rb + 8 * SW_);
            A[mt][2] = *(uint32_t*)(smem + K1W1_ + rb + 16);
            A[mt][3] = *(uint32_t*)(smem + K1W1_ + rb + 8 * SW_ + 16);
        }
        #pragma unroll
        for (int nt = 0; nt < 4; ++nt) {
            int pb = (ns * 32 + nt * 8 + g) * SW_ + koff;
            Bv[nt][0] = *(uint32_t*)(smem + K1XF_ + pb);
            Bv[nt][1] = *(uint32_t*)(smem + K1XF_ + pb + 16);
        }
        #pragma unroll
        for (int mt = 0; mt < 2; ++mt)
            #pragma unroll
            for (int nt = 0; nt < 4; ++nt)
                mma16816(acc[mt][nt], A[mt], Bv[nt]);
    }

    // epilogue: relu(acc + sh1) -> fp16 -> XP smem [pt][o]
    #pragma unroll
    for (int mt = 0; mt < 2; ++mt) {
        int o = mq * 32 + mt * 16 + g;
        #pragma unroll
        for (int nt = 0; nt < 4; ++nt) {
            int pt = ns * 32 + nt * 8 + q * 2;
            __half v0 = __float2half(fmaxf(acc[mt][nt][0] + sh1r[mt][0], 0.f));
            __half v1 = __float2half(fmaxf(acc[mt][nt][1] + sh1r[mt][0], 0.f));
            __half v2 = __float2half(fmaxf(acc[mt][nt][2] + sh1r[mt][1], 0.f));
            __half v3 = __float2half(fmaxf(acc[mt][nt][3] + sh1r[mt][1], 0.f));
            *(__half*)(smem + K1XP_ + pt * SW_ + o * 2) = v0;
            *(__half*)(smem + K1XP_ + (pt + 1) * SW_ + o * 2) = v1;
            *(__half*)(smem + K1XP_ + pt * SW_ + (o + 8) * 2) = v2;
            *(__half*)(smem + K1XP_ + (pt + 1) * SW_ + (o + 8) * 2) = v3;
        }
    }
    __syncthreads();

    // coalesced store: 128 rows x 128B -> g_p
    __half* pb = g_p + ((size_t)b * N_ + n0) * 64;
    #pragma unroll
    for (int it = 0; it < 4; ++it) {
        int i = it * 256 + tid;
        int row = i >> 3, e = i & 7;
        *(uint4*)(pb + (size_t)row * 64 + e * 8) =
            *(const uint4*)(smem + K1XP_ + row * SW_ + e * 16);
    }
}

// ---------------- K2: persistent fp16 HMMA, 256 thr, 3 CTA/SM, sequential GEMMs ----------------
#define W2_ 0
#define W3_ 18432
#define XH_ 36864
#define XF_ 46080
#define CTRL_ 55296
#define SMEM2_ 55328

__global__ __launch_bounds__(256, 3) void k2_kernel(const float* __restrict__ f,
                                                    const int* __restrict__ nidx,
                                                    float* __restrict__ out,
                                                    const float* __restrict__ w2,
                                                    const float* __restrict__ g2,
                                                    const float* __restrict__ b2,
                                                    const float* __restrict__ m2,
                                                    const float* __restrict__ v2,
                                                    const float* __restrict__ w3,
                                                    const float* __restrict__ g3,
                                                    const float* __restrict__ b3,
                                                    const float* __restrict__ m3,
                                                    const float* __restrict__ v3) {
    extern __shared__ __align__(16) char smem[];
    const int tid = threadIdx.x;
    const int wid = tid >> 5, lane = tid & 31;
    const int g = lane >> 2, q = lane & 3;
    const int mq = wid >> 1, ns = wid & 1;
    const uint32_t sb = smem_u32(smem);

    const uint32_t a_lane = (lane & 7) * SW_ + ((lane >> 3) & 1) * (8 * SW_) + (lane >> 4) * 16;
    const uint32_t b_lane = ((lane >> 4) * 8 + (lane & 7)) * SW_ + ((lane >> 3) & 1) * 16;

    // fuse + convert w2/w3 -> fp16 padded smem (once per CTA)
    #pragma unroll
    for (int i = tid; i < D_ * C_; i += 256) {
        int o = i >> 6, c = i & 63;
        float sc2 = g2[o] * rsqrtf(v2[o] + EPS_);
        *(__half*)(smem + W2_ + o * SW_ + c * 2) = __float2half(w2[i] * sc2);
        float sc3 = g3[o] * rsqrtf(v3[o] + EPS_);
        *(__half*)(smem + W3_ + o * SW_ + c * 2) = __float2half(w3[i] * sc3);
    }
    float sh2r[2][2], sh3r[2][2];
    #pragma unroll
    for (int mt = 0; mt < 2; ++mt) {
        int o = mq * 32 + mt * 16 + g;
        sh2r[mt][0] = b2[o] - m2[o] * (g2[o] * rsqrtf(v2[o] + EPS_));
        sh2r[mt][1] = b2[o + 8] - m2[o + 8] * (g2[o + 8] * rsqrtf(v2[o + 8] + EPS_));
        sh3r[mt][0] = b3[o] - m3[o] * (g3[o] * rsqrtf(v3[o] + EPS_));
        sh3r[mt][1] = b3[o + 8] - m3[o + 8] * (g3[o + 8] * rsqrtf(v3[o + 8] + EPS_));
    }
    int* ctrl = (int*)(smem + CTRL_);

    for (;;) {
        __syncthreads();
        if (tid == 0) ctrl[0] = atomicAdd(&g_ticket, 1);
        __syncthreads();
        const int t = ctrl[0];
        if (t >= TILES_) break;
        const int b = t / (N_ / NT_);
        const int n0 = (t % (N_ / NT_)) * NT_;

        // --- transpose f tile -> XF fp16: 64ch x 64pt ---
        const float* fb = f + (size_t)b * C_ * N_ + n0;
        #pragma unroll
        for (int it = 0; it < 8; ++it) {
            int idx = it * 256 + tid;
            int j = idx & 63, c = (idx >> 6) * 2;
            float x0 = fb[(size_t)c * N_ + j];
            float x1 = fb[(size_t)(c + 1) * N_ + j];
            __half2 h2 = __floats2half2_rn(x0, x1);
            *(uint32_t*)(smem + XF_ + j * SW_ + c * 2) = *(uint32_t*)&h2;
        }

        // --- gather-sum p: 8 lanes per 128B row; fp16 group-of-4 tree + fp32 across groups ---
        {
            const int e = tid & 7;
            const __half* pbase = g_p + (size_t)b * N_ * 64 + e * 8;
            const int4* ibase = (const int4*)(nidx + ((size_t)b * N_ + n0) * 16);
            #pragma unroll
            for (int p4 = 0; p4 < 2; ++p4) {
                const int j = (tid >> 3) + p4 * 32;
                float2 acc[4];
                #pragma unroll
                for (int u = 0; u < 4; ++u) acc[u] = make_float2(0.f, 0.f);
                #pragma unroll
                for (int h8 = 0; h8 < 2; ++h8) {
                    int4 idA = ibase[j * 4 + h8 * 2];
                    int4 idB = ibase[j * 4 + h8 * 2 + 1];
                    int ids[8] = {idA.x, idA.y, idA.z, idA.w, idB.x, idB.y, idB.z, idB.w};
                    uint4 v[8];
                    #pragma unroll
                    for (int k = 0; k < 8; ++k)
                        v[k] = *(const uint4*)(pbase + (size_t)ids[k] * 64);
                    #pragma unroll
                    for (int gg = 0; gg < 2; ++gg) {
                        uint4 s = hadd2_u4(hadd2_u4(v[4 * gg], v[4 * gg + 1]),
                                           hadd2_u4(v[4 * gg + 2], v[4 * gg + 3]));
                        const __half2* hp = (const __half2*)&s;
                        #pragma unroll
                        for (int u = 0; u < 4; ++u) {
                            float2 fv = __half22float2(hp[u]);
                            acc[u].x += fv.x;
                            acc[u].y += fv.y;
                        }
                    }
                }
                __half2 hh[4];
                #pragma unroll
                for (int u = 0; u < 4; ++u)
                    hh[u] = __floats2half2_rn(acc[u].x, acc[u].y);
                *(uint4*)(smem + XH_ + j * SW_ + e * 16) = *(uint4*)hh;
            }
        }
        __syncthreads();

        // --- sequential GEMMs (shared accumulator block, 3 CTA/SM) ---
        const int obase = mq * 32;
        float* outb = out + (size_t)b * D_ * N_ + n0;
        float acc[2][4][4];
        uint32_t sreg[2][4][2];   // packed fp16x2 partial: relu(s + sh3)

        // GEMM2: W3 x F -> packed partial
        #pragma unroll
        for (int mt = 0; mt < 2; ++mt)
            #pragma unroll
            for (int nt = 0; nt < 4; ++nt)
                #pragma unroll
                for (int e = 0; e < 4; ++e) acc[mt][nt][e] = 0.f;
        #pragma unroll
        for (int k = 0; k < 4; ++k) {
            const uint32_t kb = 32 * k;
            uint32_t Ar[2][4], Br[2][4];
            ldsm4(Ar[0], sb + W3_ + (uint32_t)obase * SW_ + kb + a_lane);
            ldsm4(Ar[1], sb + W3_ + (uint32_t)(obase + 16) * SW_ + kb + a_lane);
            ldsm4(Br[0], sb + XF_ + (uint32_t)(ns * 32) * SW_ + kb + b_lane);
            ldsm4(Br[1], sb + XF_ + (uint32_t)(ns * 32 + 16) * SW_ + kb + b_lane);
            #pragma unroll
            for (int mt = 0; mt < 2; ++mt)
                #pragma unroll
                for (int nt = 0; nt < 4; ++nt)
                    mma16816(acc[mt][nt], Ar[mt], &Br[nt >> 1][(nt & 1) * 2]);
        }
        #pragma unroll
        for (int mt = 0; mt < 2; ++mt)
            #pragma unroll
            for (int nt = 0; nt < 4; ++nt) {
                __half2 p0 = __floats2half2_rn(fmaxf(acc[mt][nt][0] + sh3r[mt][0], 0.f),
                                               fmaxf(acc[mt][nt][1] + sh3r[mt][0], 0.f));
                __half2 p1 = __floats2half2_rn(fmaxf(acc[mt][nt][2] + sh3r[mt][1], 0.f),
                                               fmaxf(acc[mt][nt][3] + sh3r[mt][1], 0.f));
                sreg[mt][nt][0] = *(uint32_t*)&p0;
                sreg[mt][nt][1] = *(uint32_t*)&p1;
            }

        // GEMM1: W2 x Hsum (reuse acc)
        #pragma unroll
        for (int mt = 0; mt < 2; ++mt)
            #pragma unroll
            for (int nt = 0; nt < 4; ++nt)
                #pragma unroll
                for (int e = 0; e < 4; ++e) acc[mt][nt][e] = 0.f;
        #pragma unroll
        for (int k = 0; k < 4; ++k) {
            const uint32_t kb = 32 * k;
            uint32_t Ar[2][4], Br[2][4];
            ldsm4(Ar[0], sb + W2_ + (uint32_t)obase * SW_ + kb + a_lane);
            ldsm4(Ar[1], sb + W2_ + (uint32_t)(obase + 16) * SW_ + kb + a_lane);
            ldsm4(Br[0], sb + XH_ + (uint32_t)(ns * 32) * SW_ + kb + b_lane);
            ldsm4(Br[1], sb + XH_ + (uint32_t)(ns * 32 + 16) * SW_ + kb + b_lane);
            #pragma unroll
            for (int mt = 0; mt < 2; ++mt)
                #pragma unroll
                for (int nt = 0; nt < 4; ++nt)
                    mma16816(acc[mt][nt], Ar[mt], &Br[nt >> 1][(nt & 1) * 2]);
        }

        // --- epilogue: res = relu(h+sh2) + partial_s ---
        #pragma unroll
        for (int mt = 0; mt < 2; ++mt) {
            int o = obase + mt * 16 + g;
            #pragma unroll
            for (int nt = 0; nt < 4; ++nt) {
                int col = ns * 32 + nt * 8 + q * 2;
                float2 s0 = __half22float2(*(__half2*)&sreg[mt][nt][0]);
                float2 s1 = __half22float2(*(__half2*)&sreg[mt][nt][1]);
                float2 v0, v1;
                v0.x = fmaxf(acc[mt][nt][0] + sh2r[mt][0], 0.f) + s0.x;
                v0.y = fmaxf(acc[mt][nt][1] + sh2r[mt][0], 0.f) + s0.y;
                v1.x = fmaxf(acc[mt][nt][2] + sh2r[mt][1], 0.f) + s1.x;
                v1.y = fmaxf(acc[mt][nt][3] + sh2r[mt][1], 0.f) + s1.y;
                *(float2*)(outb + (size_t)o * N_ + col) = v0;
                *(float2*)(outb + (size_t)(o + 8) * N_ + col) = v1;
            }
        }
    }
}

extern "C" void kernel_launch(void* const* d_in, const int* in_sizes, int n_in,
                              void* d_out, int out_size) {
    const float* feature = (const float*)d_in[0];
    const int* nidx = (const int*)d_in[1];
    const float* w1 = (const float*)d_in[2];
    const float* g1 = (const float*)d_in[3];
    const float* b1 = (const float*)d_in[4];
    const float* m1 = (const float*)d_in[5];
    const float* v1 = (const float*)d_in[6];
    const float* w2 = (const float*)d_in[7];
    const float* g2 = (const float*)d_in[8];
    const float* b2 = (const float*)d_in[9];
    const float* m2 = (const float*)d_in[10];
    const float* v2 = (const float*)d_in[11];
    const float* w3 = (const float*)d_in[12];
    const float* g3 = (const float*)d_in[13];
    const float* b3 = (const float*)d_in[14];
    const float* m3 = (const float*)d_in[15];
    const float* v3 = (const float*)d_in[16];
    float* out = (float*)d_out;

    cudaFuncSetAttribute(k1_kernel, cudaFuncAttributeMaxDynamicSharedMemorySize, SMEM1_);
    cudaFuncSetAttribute(k2_kernel, cudaFuncAttributeMaxDynamicSharedMemorySize, SMEM2_);

    k1_kernel<<<dim3(N_ / 128, B_), 256, SMEM1_>>>(feature, w1, g1, b1, m1, v1);
    k2_kernel<<<456, 256, SMEM2_>>>(feature, nidx, out,
                                    w2, g2, b2, m2, v2, w3, g3, b3, m3, v3);
}

// round 17
// speedup vs baseline: 1.0692x; 1.0208x over previous
#include <cuda_runtime.h>
#include <cuda_bf16.h>
#include <cuda_fp16.h>
#include <cstdint>

#define B_ 4
#define C_ 64
#define N_ 40960
#define K_ 16
#define D_ 128
#define EPS_ 1e-5f
#define NT_ 64
#define TILES_ 2560   // B_ * N_/NT_

// ---------------- global scratch ----------------
__device__ __half g_p[(size_t)B_ * N_ * C_];   // relu(BN1(w1@f)) per point, fp16 128B rows
__device__ __half g_w1h[C_ * C_];              // fused w1, fp16, [o][c]
__device__ __half g_w2h[D_ * C_];              // fused w2, fp16, [o][c]
__device__ __half g_w3h[D_ * C_];              // fused w3, fp16, [o][c]
__device__ float g_sh1[C_], g_sh2[D_], g_sh3[D_];
__device__ int g_ticket;

// ---------------- helpers ----------------
__device__ __forceinline__ void mma16816(float* d, const uint32_t* a, const uint32_t* b) {
    asm volatile(
        "mma.sync.aligned.m16n8k16.row.col.f32.f16.f16.f32 "
        "{%0,%1,%2,%3}, {%4,%5,%6,%7}, {%8,%9}, {%0,%1,%2,%3};\n"
        : "+f"(d[0]), "+f"(d[1]), "+f"(d[2]), "+f"(d[3])
        : "r"(a[0]), "r"(a[1]), "r"(a[2]), "r"(a[3]), "r"(b[0]), "r"(b[1]));
}

__device__ __forceinline__ void ldsm4(uint32_t* r, uint32_t addr) {
    asm volatile("ldmatrix.sync.aligned.m8n8.x4.shared.b16 {%0,%1,%2,%3}, [%4];"
                 : "=r"(r[0]), "=r"(r[1]), "=r"(r[2]), "=r"(r[3]) : "r"(addr));
}

__device__ __forceinline__ uint32_t smem_u32(const void* p) {
    uint32_t a;
    asm("{ .reg .u64 t; cvta.to.shared.u64 t, %1; cvt.u32.u64 %0, t; }" : "=r"(a) : "l"(p));
    return a;
}

// ---------------- prep: fuse BN into weights (fp16), shifts (fp32), reset ticket ----------------
__global__ void prep_kernel(const float* __restrict__ w1, const float* __restrict__ g1,
                            const float* __restrict__ b1, const float* __restrict__ m1,
                            const float* __restrict__ v1,
                            const float* __restrict__ w2, const float* __restrict__ g2,
                            const float* __restrict__ b2, const float* __restrict__ m2,
                            const float* __restrict__ v2,
                            const float* __restrict__ w3, const float* __restrict__ g3,
                            const float* __restrict__ b3, const float* __restrict__ m3,
                            const float* __restrict__ v3) {
    const int t = blockIdx.x * blockDim.x + threadIdx.x;
    const int stride = gridDim.x * blockDim.x;
    if (t == 0) g_ticket = 0;
    for (int i = t; i < C_ * C_; i += stride) {
        int o = i >> 6;
        float sc = g1[o] * rsqrtf(v1[o] + EPS_);
        g_w1h[i] = __float2half(w1[i] * sc);
    }
    for (int i = t; i < D_ * C_; i += stride) {
        int o = i >> 6;
        float sc2 = g2[o] * rsqrtf(v2[o] + EPS_);
        g_w2h[i] = __float2half(w2[i] * sc2);
        float sc3 = g3[o] * rsqrtf(v3[o] + EPS_);
        g_w3h[i] = __float2half(w3[i] * sc3);
    }
    if (t < C_) {
        float sc = g1[t] * rsqrtf(v1[t] + EPS_);
        g_sh1[t] = b1[t] - m1[t] * sc;
    }
    if (t < D_) {
        float sc2 = g2[t] * rsqrtf(v2[t] + EPS_);
        g_sh2[t] = b2[t] - m2[t] * sc2;
        float sc3 = g3[t] * rsqrtf(v3[t] + EPS_);
        g_sh3[t] = b3[t] - m3[t] * sc3;
    }
}

// ---------------- K1: p = relu(BN1(w1 @ f)) via fp16 HMMA ----------------
// Tile = 128 points. XF/XP [pt][ch] fp16, 144B pitch; W1 [o][c] fp16, 144B pitch.
#define SW_ 144
#define K1W1_ 0
#define K1XF_ 9216
#define K1XP_ 27648
#define SMEM1_ 46080

__global__ __launch_bounds__(256, 2) void k1_kernel(const float* __restrict__ f) {
    extern __shared__ __align__(16) char smem[];
    const int tid = threadIdx.x;
    const int wid = tid >> 5, lane = tid & 31;
    const int g = lane >> 2, q = lane & 3;
    const int mq = wid >> 2, ns = wid & 3;
    const int b = blockIdx.y;
    const int n0 = blockIdx.x * 128;

    // stage preconverted w1 fp16 into padded smem
    #pragma unroll
    for (int i = tid; i < 512; i += 256) {
        int o = i >> 3, p8 = i & 7;
        *(uint4*)(smem + K1W1_ + o * SW_ + p8 * 16) = ((const uint4*)g_w1h)[i];
    }
    float sh1r[2][2];
    #pragma unroll
    for (int mt = 0; mt < 2; ++mt) {
        int o = mq * 32 + mt * 16 + g;
        sh1r[mt][0] = g_sh1[o];
        sh1r[mt][1] = g_sh1[o + 8];
    }

    // transpose f tile -> XF fp16 [pt][ch]
    const float* fb = f + (size_t)b * C_ * N_ + n0;
    #pragma unroll
    for (int it = 0; it < 16; ++it) {
        int idx = it * 256 + tid;
        int j = idx & 127, c = (idx >> 7) * 2;
        float x0 = fb[(size_t)c * N_ + j];
        float x1 = fb[(size_t)(c + 1) * N_ + j];
        __half2 h2 = __floats2half2_rn(x0, x1);
        *(uint32_t*)(smem + K1XF_ + j * SW_ + c * 2) = *(uint32_t*)&h2;
    }
    __syncthreads();

    // MMA: warp = rows [mq*32,+32) x pts [ns*32,+32)
    float acc[2][4][4];
    #pragma unroll
    for (int mt = 0; mt < 2; ++mt)
        #pragma unroll
        for (int nt = 0; nt < 4; ++nt)
            #pragma unroll
            for (int e = 0; e < 4; ++e) acc[mt][nt][e] = 0.f;

    #pragma unroll
    for (int k = 0; k < 4; ++k) {
        const int koff = 32 * k + 4 * q;
        uint32_t A[2][4], Bv[4][2];
        #pragma unroll
        for (int mt = 0; mt < 2; ++mt) {
            int rb = (mq * 32 + mt * 16 + g) * SW_ + koff;
            A[mt][0] = *(uint32_t*)(smem + K1W1_ + rb);
            A[mt][1] = *(uint32_t*)(smem + K1W1_ + rb + 8 * SW_);
            A[mt][2] = *(uint32_t*)(smem + K1W1_ + rb + 16);
            A[mt][3] = *(uint32_t*)(smem + K1W1_ + rb + 8 * SW_ + 16);
        }
        #pragma unroll
        for (int nt = 0; nt < 4; ++nt) {
            int pb = (ns * 32 + nt * 8 + g) * SW_ + koff;
            Bv[nt][0] = *(uint32_t*)(smem + K1XF_ + pb);
            Bv[nt][1] = *(uint32_t*)(smem + K1XF_ + pb + 16);
        }
        #pragma unroll
        for (int mt = 0; mt < 2; ++mt)
            #pragma unroll
            for (int nt = 0; nt < 4; ++nt)
                mma16816(acc[mt][nt], A[mt], Bv[nt]);
    }

    // epilogue: relu(acc + sh1) -> fp16 -> XP smem [pt][o]
    #pragma unroll
    for (int mt = 0; mt < 2; ++mt) {
        int o = mq * 32 + mt * 16 + g;
        #pragma unroll
        for (int nt = 0; nt < 4; ++nt) {
            int pt = ns * 32 + nt * 8 + q * 2;
            __half v0 = __float2half(fmaxf(acc[mt][nt][0] + sh1r[mt][0], 0.f));
            __half v1 = __float2half(fmaxf(acc[mt][nt][1] + sh1r[mt][0], 0.f));
            __half v2 = __float2half(fmaxf(acc[mt][nt][2] + sh1r[mt][1], 0.f));
            __half v3 = __float2half(fmaxf(acc[mt][nt][3] + sh1r[mt][1], 0.f));
            *(__half*)(smem + K1XP_ + pt * SW_ + o * 2) = v0;
            *(__half*)(smem + K1XP_ + (pt + 1) * SW_ + o * 2) = v1;
            *(__half*)(smem + K1XP_ + pt * SW_ + (o + 8) * 2) = v2;
            *(__half*)(smem + K1XP_ + (pt + 1) * SW_ + (o + 8) * 2) = v3;
        }
    }
    __syncthreads();

    // coalesced store: 128 rows x 128B -> g_p
    __half* pb = g_p + ((size_t)b * N_ + n0) * 64;
    #pragma unroll
    for (int it = 0; it < 4; ++it) {
        int i = it * 256 + tid;
        int row = i >> 3, e = i & 7;
        *(uint4*)(pb + (size_t)row * 64 + e * 8) =
            *(const uint4*)(smem + K1XP_ + row * SW_ + e * 16);
    }
}

// ---------------- K2: persistent fp16 HMMA, 256 thr, 3 CTA/SM, sequential GEMMs ----------------
#define W2_ 0
#define W3_ 18432
#define XH_ 36864
#define XF_ 46080
#define CTRL_ 55296
#define SMEM2_ 55328

__global__ __launch_bounds__(256, 3) void k2_kernel(const float* __restrict__ f,
                                                    const int* __restrict__ nidx,
                                                    float* __restrict__ out) {
    extern __shared__ __align__(16) char smem[];
    const int tid = threadIdx.x;
    const int wid = tid >> 5, lane = tid & 31;
    const int g = lane >> 2, q = lane & 3;
    const int mq = wid >> 1, ns = wid & 1;
    const uint32_t sb = smem_u32(smem);

    const uint32_t a_lane = (lane & 7) * SW_ + ((lane >> 3) & 1) * (8 * SW_) + (lane >> 4) * 16;
    const uint32_t b_lane = ((lane >> 4) * 8 + (lane & 7)) * SW_ + ((lane >> 3) & 1) * 16;

    // stage preconverted fp16 weights into padded smem (once per CTA, uint4 copies)
    #pragma unroll
    for (int i = tid; i < 1024; i += 256) {
        int o = i >> 3, p8 = i & 7;
        uint32_t dst = o * SW_ + p8 * 16;
        *(uint4*)(smem + W2_ + dst) = ((const uint4*)g_w2h)[i];
        *(uint4*)(smem + W3_ + dst) = ((const uint4*)g_w3h)[i];
    }
    float sh2r[2][2], sh3r[2][2];
    #pragma unroll
    for (int mt = 0; mt < 2; ++mt) {
        int o = mq * 32 + mt * 16 + g;
        sh2r[mt][0] = g_sh2[o];     sh2r[mt][1] = g_sh2[o + 8];
        sh3r[mt][0] = g_sh3[o];     sh3r[mt][1] = g_sh3[o + 8];
    }
    int* ctrl = (int*)(smem + CTRL_);

    for (;;) {
        __syncthreads();
        if (tid == 0) ctrl[0] = atomicAdd(&g_ticket, 1);
        __syncthreads();
        const int t = ctrl[0];
        if (t >= TILES_) break;
        const int b = t / (N_ / NT_);
        const int n0 = (t % (N_ / NT_)) * NT_;

        // --- transpose f tile -> XF fp16: 64ch x 64pt ---
        const float* fb = f + (size_t)b * C_ * N_ + n0;
        #pragma unroll
        for (int it = 0; it < 8; ++it) {
            int idx = it * 256 + tid;
            int j = idx & 63, c = (idx >> 6) * 2;
            float x0 = fb[(size_t)c * N_ + j];
            float x1 = fb[(size_t)(c + 1) * N_ + j];
            __half2 h2 = __floats2half2_rn(x0, x1);
            *(uint32_t*)(smem + XF_ + j * SW_ + c * 2) = *(uint32_t*)&h2;
        }

        // --- gather-sum p: 8 lanes per 128B row, fp32 accumulate; idx from gmem ---
        {
            const int e = tid & 7;
            const __half* pbase = g_p + (size_t)b * N_ * 64 + e * 8;
            const int4* ibase = (const int4*)(nidx + ((size_t)b * N_ + n0) * 16);
            #pragma unroll
            for (int p4 = 0; p4 < 2; ++p4) {
                const int j = (tid >> 3) + p4 * 32;
                int4 id4[4];
                #pragma unroll
                for (int u = 0; u < 4; ++u) id4[u] = ibase[j * 4 + u];
                int ids[16] = {id4[0].x, id4[0].y, id4[0].z, id4[0].w,
                               id4[1].x, id4[1].y, id4[1].z, id4[1].w,
                               id4[2].x, id4[2].y, id4[2].z, id4[2].w,
                               id4[3].x, id4[3].y, id4[3].z, id4[3].w};
                float2 acc[4];
                #pragma unroll
                for (int u = 0; u < 4; ++u) acc[u] = make_float2(0.f, 0.f);
                #pragma unroll
                for (int k = 0; k < 16; ++k) {
                    uint4 v = *(const uint4*)(pbase + (size_t)ids[k] * 64);
                    const __half2* hp = (const __half2*)&v;
                    #pragma unroll
                    for (int u = 0; u < 4; ++u) {
                        float2 fv = __half22float2(hp[u]);
                        acc[u].x += fv.x;
                        acc[u].y += fv.y;
                    }
                }
                __half2 hh[4];
                #pragma unroll
                for (int u = 0; u < 4; ++u)
                    hh[u] = __floats2half2_rn(acc[u].x, acc[u].y);
                *(uint4*)(smem + XH_ + j * SW_ + e * 16) = *(uint4*)hh;
            }
        }
        __syncthreads();

        // --- sequential GEMMs (shared accumulator block, 3 CTA/SM) ---
        const int obase = mq * 32;
        float* outb = out + (size_t)b * D_ * N_ + n0;
        float acc[2][4][4];
        uint32_t sreg[2][4][2];   // packed fp16x2 partial: relu(s + sh3)

        // GEMM2: W3 x F -> packed partial
        #pragma unroll
        for (int mt = 0; mt < 2; ++mt)
            #pragma unroll
            for (int nt = 0; nt < 4; ++nt)
                #pragma unroll
                for (int e = 0; e < 4; ++e) acc[mt][nt][e] = 0.f;
        #pragma unroll
        for (int k = 0; k < 4; ++k) {
            const uint32_t kb = 32 * k;
            uint32_t Ar[2][4], Br[2][4];
            ldsm4(Ar[0], sb + W3_ + (uint32_t)obase * SW_ + kb + a_lane);
            ldsm4(Ar[1], sb + W3_ + (uint32_t)(obase + 16) * SW_ + kb + a_lane);
            ldsm4(Br[0], sb + XF_ + (uint32_t)(ns * 32) * SW_ + kb + b_lane);
            ldsm4(Br[1], sb + XF_ + (uint32_t)(ns * 32 + 16) * SW_ + kb + b_lane);
            #pragma unroll
            for (int mt = 0; mt < 2; ++mt)
                #pragma unroll
                for (int nt = 0; nt < 4; ++nt)
                    mma16816(acc[mt][nt], Ar[mt], &Br[nt >> 1][(nt & 1) * 2]);
        }
        #pragma unroll
        for (int mt = 0; mt < 2; ++mt)
            #pragma unroll
            for (int nt = 0; nt < 4; ++nt) {
                __half2 p0 = __floats2half2_rn(fmaxf(acc[mt][nt][0] + sh3r[mt][0], 0.f),
                                               fmaxf(acc[mt][nt][1] + sh3r[mt][0], 0.f));
                __half2 p1 = __floats2half2_rn(fmaxf(acc[mt][nt][2] + sh3r[mt][1], 0.f),
                                               fmaxf(acc[mt][nt][3] + sh3r[mt][1], 0.f));
                sreg[mt][nt][0] = *(uint32_t*)&p0;
                sreg[mt][nt][1] = *(uint32_t*)&p1;
            }

        // GEMM1: W2 x Hsum (reuse acc)
        #pragma unroll
        for (int mt = 0; mt < 2; ++mt)
            #pragma unroll
            for (int nt = 0; nt < 4; ++nt)
                #pragma unroll
                for (int e = 0; e < 4; ++e) acc[mt][nt][e] = 0.f;
        #pragma unroll
        for (int k = 0; k < 4; ++k) {
            const uint32_t kb = 32 * k;
            uint32_t Ar[2][4], Br[2][4];
            ldsm4(Ar[0], sb + W2_ + (uint32_t)obase * SW_ + kb + a_lane);
            ldsm4(Ar[1], sb + W2_ + (uint32_t)(obase + 16) * SW_ + kb + a_lane);
            ldsm4(Br[0], sb + XH_ + (uint32_t)(ns * 32) * SW_ + kb + b_lane);
            ldsm4(Br[1], sb + XH_ + (uint32_t)(ns * 32 + 16) * SW_ + kb + b_lane);
            #pragma unroll
            for (int mt = 0; mt < 2; ++mt)
                #pragma unroll
                for (int nt = 0; nt < 4; ++nt)
                    mma16816(acc[mt][nt], Ar[mt], &Br[nt >> 1][(nt & 1) * 2]);
        }

        // --- epilogue: res = relu(h+sh2) + partial_s ---
        #pragma unroll
        for (int mt = 0; mt < 2; ++mt) {
            int o = obase + mt * 16 + g;
            #pragma unroll
            for (int nt = 0; nt < 4; ++nt) {
                int col = ns * 32 + nt * 8 + q * 2;
                float2 s0 = __half22float2(*(__half2*)&sreg[mt][nt][0]);
                float2 s1 = __half22float2(*(__half2*)&sreg[mt][nt][1]);
                float2 v0, v1;
                v0.x = fmaxf(acc[mt][nt][0] + sh2r[mt][0], 0.f) + s0.x;
                v0.y = fmaxf(acc[mt][nt][1] + sh2r[mt][0], 0.f) + s0.y;
                v1.x = fmaxf(acc[mt][nt][2] + sh2r[mt][1], 0.f) + s1.x;
                v1.y = fmaxf(acc[mt][nt][3] + sh2r[mt][1], 0.f) + s1.y;
                *(float2*)(outb + (size_t)o * N_ + col) = v0;
                *(float2*)(outb + (size_t)(o + 8) * N_ + col) = v1;
            }
        }
    }
}

extern "C" void kernel_launch(void* const* d_in, const int* in_sizes, int n_in,
                              void* d_out, int out_size) {
    const float* feature = (const float*)d_in[0];
    const int* nidx = (const int*)d_in[1];
    const float* w1 = (const float*)d_in[2];
    const float* g1 = (const float*)d_in[3];
    const float* b1 = (const float*)d_in[4];
    const float* m1 = (const float*)d_in[5];
    const float* v1 = (const float*)d_in[6];
    const float* w2 = (const float*)d_in[7];
    const float* g2 = (const float*)d_in[8];
    const float* b2 = (const float*)d_in[9];
    const float* m2 = (const float*)d_in[10];
    const float* v2 = (const float*)d_in[11];
    const float* w3 = (const float*)d_in[12];
    const float* g3 = (const float*)d_in[13];
    const float* b3 = (const float*)d_in[14];
    const float* m3 = (const float*)d_in[15];
    const float* v3 = (const float*)d_in[16];
    float* out = (float*)d_out;

    cudaFuncSetAttribute(k1_kernel, cudaFuncAttributeMaxDynamicSharedMemorySize, SMEM1_);
    cudaFuncSetAttribute(k2_kernel, cudaFuncAttributeMaxDynamicSharedMemorySize, SMEM2_);

    prep_kernel<<<32, 256>>>(w1, g1, b1, m1, v1, w2, g2, b2, m2, v2, w3, g3, b3, m3, v3);
    k1_kernel<<<dim3(N_ / 128, B_), 256, SMEM1_>>>(feature);
    k2_kernel<<<444, 256, SMEM2_>>>(feature, nidx, out);
}